// round 6
// baseline (speedup 1.0000x reference)
#include <cuda_runtime.h>
#include <cstddef>

#define Bc 16
#define Fc 4
#define Kc 16
#define KH 8          // k's per block (k-half)
#define Yc 16
#define Xc 16
#define Pc 16
#define Tc 8
#define NT 1024

// One block = (b, f, k-half). 1024 threads: thread = (yh:2b, x:4b, p:4b),
// 4 y-rows of 8 t-values for 8 k's. Pure scalar FFMA (no f32x2 asm):
// per row: ft[t] = f*dt (8 MUL), per k: Horner in r over t (7 FMA) + 1 FMA
// accumulate with weight sklatda[y][x][k] = klat[y][k]*darea[y][x] (LDS).
__global__ void __launch_bounds__(NT, 1) pkl_fused(
    const float* __restrict__ field, const float* __restrict__ darea,
    const float* __restrict__ dlev,  const float* __restrict__ dtime,
    const float* __restrict__ lat_mean, const float* __restrict__ lat_logstd,
    const float* __restrict__ lon_mean, const float* __restrict__ lon_logstd,
    const float* __restrict__ lev_mean, const float* __restrict__ lev_logstd,
    const float* __restrict__ time_logtau, float* __restrict__ out)
{
    int blk = blockIdx.x;
    int kh = blk & 1;
    int f  = (blk >> 1) & 3;
    int b  = blk >> 3;
    int tid  = threadIdx.x;
    int lane = tid & 31;
    int warp = tid >> 5;

    __shared__ __align__(16) float sklat[Yc][KH];
    __shared__ __align__(16) float sklon[Xc][KH];
    __shared__ __align__(16) float sklev[Pc][KH];
    __shared__ __align__(16) float sklatda[Yc * Xc * KH];  // klat[y][k]*darea[y][x]
    __shared__ float srate[KH], swinv[KH];
    __shared__ float sdamean[Yc * Xc], sda[Yc * Xc];
    __shared__ float sdlmean[Pc], sdl[Pc], sdtm[Tc], sdt[Tc];
    __shared__ float sred[32][KH];

    // ================= phase 1: params, means =================
    if (tid < 3 * 16 * KH) {
        int j   = tid & 7;
        int d   = (tid >> 3) & 15;
        int dim = tid >> 7;
        int fk  = f * Kc + kh * KH + j;
        float coord = -1.0f + 2.0f * (float)d / 15.0f;
        float m, ls;
        if (dim == 0)      { m = lat_mean[fk]; ls = lat_logstd[fk]; }
        else if (dim == 1) { m = lon_mean[fk]; ls = lon_logstd[fk]; }
        else               { m = lev_mean[fk]; ls = lev_logstd[fk]; }
        float z = (coord - m) * expf(-ls);
        float g = expf(-0.5f * z * z);
        if (dim == 0)      sklat[d][j] = g;
        else if (dim == 1) sklon[d][j] = g;
        else               sklev[d][j] = g;
    }
    if (tid >= 512 && tid < 512 + KH) {
        int j = tid - 512;
        int fk = f * Kc + kh * KH + j;
        float tau = expf(time_logtau[fk]) + 1e-4f;
        srate[j] = expf(-1.0f / tau);      // ktime[t] = r^t
    }
    if (tid >= 768) {
        int i = tid - 768;
        float s = 0.f;
        #pragma unroll
        for (int bb = 0; bb < Bc; bb++) s += darea[bb * 256 + i];
        sdamean[i] = s * (1.f / 16.f);
        sda[i] = darea[b * 256 + i];
    }
    if (tid >= 704 && tid < 704 + Pc) {
        int i = tid - 704;
        float s = 0.f;
        #pragma unroll
        for (int bb = 0; bb < Bc; bb++) s += dlev[bb * Pc + i];
        sdlmean[i] = s * (1.f / 16.f);
        sdl[i] = dlev[b * Pc + i];
    }
    if (tid >= 736 && tid < 736 + Tc) {
        int i = tid - 736;
        float s = 0.f;
        #pragma unroll
        for (int bb = 0; bb < Bc; bb++) s += dtime[bb * Tc + i];
        sdtm[i] = s * (1.f / 16.f);
        sdt[i] = dtime[b * Tc + i];
    }
    __syncthreads();

    // ================= phase 2: weight table + normalization integral ======
    {
        // sklatda[((y*16+x)*8)+k] = klat[y][k] * darea[y][x]; 2048 entries
        #pragma unroll
        for (int rep = 0; rep < 2; rep++) {
            int i = tid + rep * 1024;
            int k = i & 7;
            int yx = i >> 3;
            int y = yx >> 4;
            sklatda[i] = sklat[y][k] * sda[yx];
        }
    }
    {
        float c[KH];
        #pragma unroll
        for (int j = 0; j < KH; j++) c[j] = 0.f;
        if (tid < 256) {
            int yi = tid >> 4, xi = tid & 15;
            float dm = sdamean[tid];
            #pragma unroll
            for (int j = 0; j < KH; j++) c[j] = dm * sklat[yi][j] * sklon[xi][j];
        }
        if (warp < 8) {
            #pragma unroll
            for (int j = 0; j < KH; j++) {
                float v = c[j];
                #pragma unroll
                for (int o = 16; o > 0; o >>= 1) v += __shfl_xor_sync(0xFFFFFFFFu, v, o);
                if (lane == 0) sred[warp][j] = v;
            }
        }
        __syncthreads();
        if (tid < KH) {
            float Syx = 0.f;
            #pragma unroll
            for (int w = 0; w < 8; w++) Syx += sred[w][tid];
            float Sp = 0.f;
            #pragma unroll
            for (int pp = 0; pp < Pc; pp++) Sp = fmaf(sklev[pp][tid], sdlmean[pp], Sp);
            float r = srate[tid];
            float St = sdtm[Tc - 1];
            #pragma unroll
            for (int t = Tc - 2; t >= 0; t--) St = fmaf(St, r, sdtm[t]);
            swinv[tid] = 1.0f / (Syx * Sp * St + 1e-4f);
        }
        __syncthreads();   // table + swinv visible; sred free for reuse
    }

    // ================= main contraction =================
    int p  = tid & 15;
    int x  = (tid >> 4) & 15;
    int yh = tid >> 8;                     // 0..3
    int y0 = yh * 4;

    const float4* src = (const float4*)(field
        + (size_t)(b * Fc + f) * (Yc * Xc * Pc * Tc)
        + (y0 * Xc * Pc + x * Pc + p) * Tc);
    // y-stride = 2048 floats = 512 float4

    float rate[KH];
    #pragma unroll
    for (int k = 0; k < KH; k++) rate[k] = srate[k];
    float dtr[Tc];
    #pragma unroll
    for (int t = 0; t < Tc; t++) dtr[t] = sdt[t];
    float acc[KH];
    #pragma unroll
    for (int k = 0; k < KH; k++) acc[k] = 0.f;

    // pipeline depth 2: rows 0,1 preloaded; row yy+2 prefetched in-loop
    float4 va[2][2];
    va[0][0] = src[0];    va[0][1] = src[1];
    va[1][0] = src[512];  va[1][1] = src[513];

    const float* wbase = &sklatda[((y0 << 4) | x) << 3];   // stride 128 per y

    #pragma unroll
    for (int yy = 0; yy < 4; yy++) {
        float4 a0 = va[yy & 1][0], a1 = va[yy & 1][1];
        if (yy < 2) {
            va[yy & 1][0] = src[(yy + 2) * 512];
            va[yy & 1][1] = src[(yy + 2) * 512 + 1];
        }
        float ft0 = a0.x * dtr[0], ft1 = a0.y * dtr[1];
        float ft2 = a0.z * dtr[2], ft3 = a0.w * dtr[3];
        float ft4 = a1.x * dtr[4], ft5 = a1.y * dtr[5];
        float ft6 = a1.z * dtr[6], ft7 = a1.w * dtr[7];
        const float* w = wbase + yy * 128;
        #pragma unroll
        for (int k = 0; k < KH; k++) {
            float r = rate[k];
            float dot = fmaf(ft7, r, ft6);
            dot = fmaf(dot, r, ft5);
            dot = fmaf(dot, r, ft4);
            dot = fmaf(dot, r, ft3);
            dot = fmaf(dot, r, ft2);
            dot = fmaf(dot, r, ft1);
            dot = fmaf(dot, r, ft0);
            acc[k] = fmaf(w[k], dot, acc[k]);
        }
    }

    // (x,p)-dependent factors, once per k
    float dlp = sdl[p];
    float av[KH];
    #pragma unroll
    for (int k = 0; k < KH; k++)
        av[k] = acc[k] * (sklon[x][k] * sklev[p][k] * dlp);

    // ---- deterministic block reduction: shfl + fixed-order shared sum ----
    #pragma unroll
    for (int j = 0; j < KH; j++) {
        float v = av[j];
        #pragma unroll
        for (int o = 16; o > 0; o >>= 1) v += __shfl_xor_sync(0xFFFFFFFFu, v, o);
        if (lane == 0) sred[warp][j] = v;
    }
    __syncthreads();
    if (tid < KH) {
        float s = 0.f;
        #pragma unroll
        for (int w = 0; w < 32; w++) s += sred[w][tid];
        out[b * (Fc * Kc) + f * Kc + kh * KH + tid] = s * swinv[tid];
    }
}

extern "C" void kernel_launch(void* const* d_in, const int* in_sizes, int n_in,
                              void* d_out, int out_size)
{
    pkl_fused<<<Bc * Fc * 2, NT>>>(
        (const float*)d_in[0], (const float*)d_in[1],
        (const float*)d_in[2], (const float*)d_in[3],
        (const float*)d_in[4], (const float*)d_in[5],
        (const float*)d_in[6], (const float*)d_in[7],
        (const float*)d_in[8], (const float*)d_in[9],
        (const float*)d_in[10], (float*)d_out);
}

// round 7
// speedup vs baseline: 1.0426x; 1.0426x over previous
#include <cuda_runtime.h>
#include <cstddef>

#define Bc 16
#define Fc 4
#define Kc 16
#define KH 8          // k's per block (k-half)
#define Yc 16
#define Xc 16
#define Pc 16
#define Tc 8
#define NT 1024

typedef unsigned long long u64;

// sm_103a packed f32x2 ops (PTX-only)
__device__ __forceinline__ u64 pk2(float lo, float hi) {
    u64 r; asm("mov.b64 %0, {%1,%2};" : "=l"(r) : "f"(lo), "f"(hi)); return r;
}
__device__ __forceinline__ void unpk2(u64 v, float& lo, float& hi) {
    asm("mov.b64 {%0,%1}, %2;" : "=f"(lo), "=f"(hi) : "l"(v));
}
__device__ __forceinline__ u64 fma2_(u64 a, u64 b, u64 c) {
    u64 d; asm("fma.rn.f32x2 %0, %1, %2, %3;" : "=l"(d) : "l"(a), "l"(b), "l"(c)); return d;
}
__device__ __forceinline__ u64 mul2_(u64 a, u64 b) {
    u64 d; asm("mul.rn.f32x2 %0, %1, %2;" : "=l"(d) : "l"(a), "l"(b)); return d;
}

// One block = (b, f, k-half). 1024 threads: thread = (yh:2b, x:4b, p:4b),
// 4 y-rows of 8 t-values for 8 k's.
// Inner loop: q_i = (f2i,f2i+1) * (dt2i,dt2i+1)  [lanes = (even,odd) t],
// Horner in r^2 across q3..q0, accumulate with (klat*darea) pair from LDS.
// Odd-lane r-correction deferred past the whole y-loop. No broadcast MOVs.
__global__ void __launch_bounds__(NT, 1) pkl_fused(
    const float* __restrict__ field, const float* __restrict__ darea,
    const float* __restrict__ dlev,  const float* __restrict__ dtime,
    const float* __restrict__ lat_mean, const float* __restrict__ lat_logstd,
    const float* __restrict__ lon_mean, const float* __restrict__ lon_logstd,
    const float* __restrict__ lev_mean, const float* __restrict__ lev_logstd,
    const float* __restrict__ time_logtau, float* __restrict__ out)
{
    int blk = blockIdx.x;
    int kh = blk & 1;
    int f  = (blk >> 1) & 3;
    int b  = blk >> 3;
    int tid  = threadIdx.x;
    int lane = tid & 31;
    int warp = tid >> 5;

    // thread geometry + early field prefetch (rows 0,1 of this thread)
    int p  = tid & 15;
    int x  = (tid >> 4) & 15;
    int yh = tid >> 8;                     // 0..3
    int y0 = yh * 4;
    const ulonglong2* src = (const ulonglong2*)(field
        + (size_t)(b * Fc + f) * (Yc * Xc * Pc * Tc)
        + (y0 * Xc * Pc + x * Pc + p) * Tc);
    // y-stride = 2048 floats = 512 ulonglong2
    ulonglong2 v0 = src[0], v1 = src[1];               // row 0
    ulonglong2 w0 = src[512], w1 = src[513];           // row 1

    __shared__ __align__(16) float sklat[Yc][KH];
    __shared__ __align__(16) float sklon[Xc][KH];
    __shared__ __align__(16) float sklev[Pc][KH];
    __shared__ __align__(16) u64 sklatda2[Yc * Xc * KH]; // (klat*da, klat*da)
    __shared__ __align__(16) u64 ss2d[KH];               // (r^2, r^2)
    __shared__ __align__(16) float sdt[Tc];              // u64-pair readable
    __shared__ float srate[KH], sr2[KH];
    __shared__ float sdamean[Yc * Xc], sda[Yc * Xc];
    __shared__ float sdlmean[Pc], sdl[Pc], sdtm[Tc];
    __shared__ float sred[32][KH];
    __shared__ float sint[8][KH];          // per-warp partial Syx

    // ================= phase 1: params, means =================
    if (tid < 3 * 16 * KH) {
        int j   = tid & 7;
        int d   = (tid >> 3) & 15;
        int dim = tid >> 7;
        int fk  = f * Kc + kh * KH + j;
        float coord = -1.0f + 2.0f * (float)d / 15.0f;
        float m, ls;
        if (dim == 0)      { m = lat_mean[fk]; ls = lat_logstd[fk]; }
        else if (dim == 1) { m = lon_mean[fk]; ls = lon_logstd[fk]; }
        else               { m = lev_mean[fk]; ls = lev_logstd[fk]; }
        float z = (coord - m) * expf(-ls);
        float g = expf(-0.5f * z * z);
        if (dim == 0)      sklat[d][j] = g;
        else if (dim == 1) sklon[d][j] = g;
        else               sklev[d][j] = g;
    }
    if (tid >= 512 && tid < 512 + KH) {
        int j = tid - 512;
        int fk = f * Kc + kh * KH + j;
        float tau = expf(time_logtau[fk]) + 1e-4f;
        float r = expf(-1.0f / tau);       // ktime[t] = r^t
        srate[j] = r;
        sr2[j] = r * r;
    }
    if (tid >= 768) {
        int i = tid - 768;
        float s = 0.f;
        #pragma unroll
        for (int bb = 0; bb < Bc; bb++) s += darea[bb * 256 + i];
        sdamean[i] = s * (1.f / 16.f);
        sda[i] = darea[b * 256 + i];
    }
    if (tid >= 704 && tid < 704 + Pc) {
        int i = tid - 704;
        float s = 0.f;
        #pragma unroll
        for (int bb = 0; bb < Bc; bb++) s += dlev[bb * Pc + i];
        sdlmean[i] = s * (1.f / 16.f);
        sdl[i] = dlev[b * Pc + i];
    }
    if (tid >= 736 && tid < 736 + Tc) {
        int i = tid - 736;
        float s = 0.f;
        #pragma unroll
        for (int bb = 0; bb < Bc; bb++) s += dtime[bb * Tc + i];
        sdtm[i] = s * (1.f / 16.f);
        sdt[i] = dtime[b * Tc + i];
    }
    __syncthreads();

    // ================= phase 2: pair tables + partial integral =================
    #pragma unroll
    for (int rep = 0; rep < 2; rep++) {
        int i = tid + rep * 1024;          // 2048 entries
        int k = i & 7;
        int yx = i >> 3;
        float v = sklat[yx >> 4][k] * sda[yx];
        sklatda2[i] = pk2(v, v);
    }
    if (tid >= 512 && tid < 512 + KH) {
        int j = tid - 512;
        float v = sr2[j];
        ss2d[j] = pk2(v, v);
    }
    {   // partial Syx per warp (warps 0-7); finalized after the main loop
        float c[KH];
        #pragma unroll
        for (int j = 0; j < KH; j++) c[j] = 0.f;
        if (tid < 256) {
            int yi = tid >> 4, xi = tid & 15;
            float dm = sdamean[tid];
            #pragma unroll
            for (int j = 0; j < KH; j++) c[j] = dm * sklat[yi][j] * sklon[xi][j];
        }
        if (warp < 8) {
            #pragma unroll
            for (int j = 0; j < KH; j++) {
                float v = c[j];
                #pragma unroll
                for (int o = 16; o > 0; o >>= 1) v += __shfl_xor_sync(0xFFFFFFFFu, v, o);
                if (lane == 0) sint[warp][j] = v;
            }
        }
    }
    __syncthreads();

    // ================= main contraction =================
    u64 dt2[4];
    {
        const u64* sdt64 = (const u64*)sdt;      // (dt0,dt1)(dt2,dt3)...
        dt2[0] = sdt64[0]; dt2[1] = sdt64[1];
        dt2[2] = sdt64[2]; dt2[3] = sdt64[3];
    }
    u64 acc2[KH];
    #pragma unroll
    for (int k = 0; k < KH; k++) acc2[k] = pk2(0.f, 0.f);

    const u64* wb = &sklatda2[((y0 << 4) | x) << 3];   // +128 per y

    #pragma unroll
    for (int yy = 0; yy < 4; yy++) {
        u64 q0 = mul2_(v0.x, dt2[0]);
        u64 q1 = mul2_(v0.y, dt2[1]);
        u64 q2 = mul2_(v1.x, dt2[2]);
        u64 q3 = mul2_(v1.y, dt2[3]);
        v0 = w0; v1 = w1;
        if (yy < 2) {
            w0 = src[(yy + 2) * 512];
            w1 = src[(yy + 2) * 512 + 1];
        }
        const u64* w = wb + yy * 128;
        #pragma unroll
        for (int k = 0; k < KH; k++) {
            u64 s2k = ss2d[k];                 // uniform LDS.64 broadcast
            u64 d = fma2_(q3, s2k, q2);        // Horner in r^2, lanes (E,O)
            d = fma2_(d, s2k, q1);
            d = fma2_(d, s2k, q0);
            acc2[k] = fma2_(w[k], d, acc2[k]); // (klat*darea) pair
        }
    }

    // deferred odd-lane correction + (x,p)-dependent factors
    float dlp = sdl[p];
    float av[KH];
    #pragma unroll
    for (int k = 0; k < KH; k++) {
        float E, O;
        unpk2(acc2[k], E, O);
        float dot = fmaf(srate[k], O, E);
        av[k] = dot * (sklon[x][k] * sklev[p][k] * dlp);
    }

    // ---- deterministic block reduction ----
    #pragma unroll
    for (int j = 0; j < KH; j++) {
        float v = av[j];
        #pragma unroll
        for (int o = 16; o > 0; o >>= 1) v += __shfl_xor_sync(0xFFFFFFFFu, v, o);
        if (lane == 0) sred[warp][j] = v;
    }
    __syncthreads();

    // ---- finalize: integral -> winv, scale, store (8 threads) ----
    if (tid < KH) {
        float s = 0.f;
        #pragma unroll
        for (int w = 0; w < 32; w++) s += sred[w][tid];
        float Syx = 0.f;
        #pragma unroll
        for (int w = 0; w < 8; w++) Syx += sint[w][tid];
        float Sp = 0.f;
        #pragma unroll
        for (int pp = 0; pp < Pc; pp++) Sp = fmaf(sklev[pp][tid], sdlmean[pp], Sp);
        float r = srate[tid];
        float St = sdtm[Tc - 1];
        #pragma unroll
        for (int t = Tc - 2; t >= 0; t--) St = fmaf(St, r, sdtm[t]);
        float winv = 1.0f / (Syx * Sp * St + 1e-4f);
        out[b * (Fc * Kc) + f * Kc + kh * KH + tid] = s * winv;
    }
}

extern "C" void kernel_launch(void* const* d_in, const int* in_sizes, int n_in,
                              void* d_out, int out_size)
{
    pkl_fused<<<Bc * Fc * 2, NT>>>(
        (const float*)d_in[0], (const float*)d_in[1],
        (const float*)d_in[2], (const float*)d_in[3],
        (const float*)d_in[4], (const float*)d_in[5],
        (const float*)d_in[6], (const float*)d_in[7],
        (const float*)d_in[8], (const float*)d_in[9],
        (const float*)d_in[10], (float*)d_out);
}